// round 1
// baseline (speedup 1.0000x reference)
#include <cuda_runtime.h>
#include <cstdint>
#include <math.h>

// ---------------------------------------------------------------------------
// UNet4LMCD: 4-level 3D U-Net, fp32 direct convolutions.
// All intermediates live in __device__ global scratch (no allocation).
// Encoder outputs are written straight into their channel slice of the
// decoder concat buffers so the "concatenate" ops are free.
// ---------------------------------------------------------------------------

#define V0_ (128*128*128)
#define V1_ (64*64*64)
#define V2_ (32*32*32)
#define V3_ (16*16*16)

__device__ float   g_s8  [64 * V3_];          // 1 MB   encoder level 8
__device__ float   g_cat2[64 * V2_];          // 8.4 MB [tconv3 out (32) | s4 (32)]
__device__ float   g_cat1[48 * V1_];          // 50 MB  [tconv2 out (32) | s2 (16)]
__device__ float   g_cat0[32u * V0_];         // 268 MB [tconv1 out (24) | s1 (8)]
__device__ double2 g_part[64 * 64];           // BN partial sums
__device__ float2  g_mstd[64];                // BN (mean, inv_std)

// ---------------------------------------------------------------------------
// Stride-1 3x3x3 conv, register tile: CG output channels x TX x-positions.
// Weights staged in shared memory. One (z, y-row-tile) block per launch cell.
// ---------------------------------------------------------------------------
template <int CG, int TX>
__global__ void conv_s1_kernel(const float* __restrict__ in,
                               const float* __restrict__ wt,
                               float* __restrict__ out,
                               int Cin, int D, int H, int W) {
    extern __shared__ float sw[];
    const int cb   = blockIdx.z * CG;
    const int tid  = threadIdx.y * blockDim.x + threadIdx.x;
    const int nthr = blockDim.x * blockDim.y;
    const int nw   = CG * Cin * 27;
    for (int i = tid; i < nw; i += nthr)
        sw[i] = wt[(size_t)cb * Cin * 27 + i];
    __syncthreads();

    const int x0 = threadIdx.x * TX;
    const int y  = blockIdx.x * blockDim.y + threadIdx.y;
    const int z  = blockIdx.y;

    float acc[CG][TX];
#pragma unroll
    for (int g = 0; g < CG; g++)
#pragma unroll
        for (int t = 0; t < TX; t++) acc[g][t] = 0.f;

    for (int ci = 0; ci < Cin; ci++) {
        const float* inc = in + (size_t)ci * D * H * W;
#pragma unroll
        for (int kd = 0; kd < 3; kd++) {
            const int iz = z + kd - 1;
            if (iz < 0 || iz >= D) continue;
#pragma unroll
            for (int kh = 0; kh < 3; kh++) {
                const int iy = y + kh - 1;
                if (iy < 0 || iy >= H) continue;
                const float* row = inc + ((size_t)iz * H + iy) * W;
                float r[TX + 2];
#pragma unroll
                for (int m = 0; m < TX + 2; m++) {
                    const int ix = x0 - 1 + m;
                    r[m] = (ix >= 0 && ix < W) ? row[ix] : 0.f;
                }
                const float* swp = sw + ci * 27 + kd * 9 + kh * 3;
#pragma unroll
                for (int g = 0; g < CG; g++) {
                    const float wv0 = swp[g * Cin * 27 + 0];
                    const float wv1 = swp[g * Cin * 27 + 1];
                    const float wv2 = swp[g * Cin * 27 + 2];
#pragma unroll
                    for (int t = 0; t < TX; t++)
                        acc[g][t] += r[t] * wv0 + r[t + 1] * wv1 + r[t + 2] * wv2;
                }
            }
        }
    }

#pragma unroll
    for (int g = 0; g < CG; g++) {
        float* orow = out + (((size_t)(cb + g) * D + z) * H + y) * W + x0;
#pragma unroll
        for (int t = 0; t < TX; t++) orow[t] = acc[g][t];
    }
}

// ---------------------------------------------------------------------------
// Stride-2 3x3x3 conv: one output voxel per thread, CG channels in registers.
// ---------------------------------------------------------------------------
template <int CG>
__global__ void conv_s2_kernel(const float* __restrict__ in,
                               const float* __restrict__ wt,
                               float* __restrict__ out,
                               int Cin, int Di, int Hi, int Wi,
                               int Do, int Ho, int Wo) {
    extern __shared__ float sw[];
    const int cb   = blockIdx.z * CG;
    const int tid  = threadIdx.y * blockDim.x + threadIdx.x;
    const int nthr = blockDim.x * blockDim.y;
    const int nw   = CG * Cin * 27;
    for (int i = tid; i < nw; i += nthr)
        sw[i] = wt[(size_t)cb * Cin * 27 + i];
    __syncthreads();

    const int x = threadIdx.x;
    const int y = blockIdx.x * blockDim.y + threadIdx.y;
    const int z = blockIdx.y;

    float acc[CG];
#pragma unroll
    for (int g = 0; g < CG; g++) acc[g] = 0.f;

    for (int ci = 0; ci < Cin; ci++) {
        const float* inc = in + (size_t)ci * Di * Hi * Wi;
#pragma unroll
        for (int kd = 0; kd < 3; kd++) {
            const int iz = 2 * z + kd - 1;
            if (iz < 0 || iz >= Di) continue;
#pragma unroll
            for (int kh = 0; kh < 3; kh++) {
                const int iy = 2 * y + kh - 1;
                if (iy < 0 || iy >= Hi) continue;
                const float* row = inc + ((size_t)iz * Hi + iy) * Wi;
#pragma unroll
                for (int kw = 0; kw < 3; kw++) {
                    const int ix = 2 * x + kw - 1;
                    if (ix < 0 || ix >= Wi) continue;
                    const float v    = row[ix];
                    const float* swp = sw + ci * 27 + kd * 9 + kh * 3 + kw;
#pragma unroll
                    for (int g = 0; g < CG; g++)
                        acc[g] += v * swp[g * Cin * 27];
                }
            }
        }
    }

#pragma unroll
    for (int g = 0; g < CG; g++)
        out[(((size_t)(cb + g) * Do + z) * Ho + y) * Wo + x] = acc[g];
}

// ---------------------------------------------------------------------------
// Stride-2 transposed 3x3x3 conv (lhs-dilated conv, pad (1,2)):
// output o gets taps from input i where d = o + k - 1, d even, i = d/2.
// Even o -> one tap (k=1); odd o -> two taps (k=0 and k=2).
// Register tile CG x TX (TX even), weights chunked through shared memory
// (chunks of <=32 input channels to stay under 48 KB smem).
// ---------------------------------------------------------------------------
template <int CG, int TX>
__global__ void tconv_kernel(const float* __restrict__ in,
                             const float* __restrict__ wt,
                             float* __restrict__ out,
                             int Cin, int Di, int Hi, int Wi) {
    const int Do = 2 * Di, Ho = 2 * Hi, Wo = 2 * Wi;
    extern __shared__ float sw[];
    const int cb   = blockIdx.z * CG;
    const int tid  = threadIdx.y * blockDim.x + threadIdx.x;
    const int nthr = blockDim.x * blockDim.y;

    const int x0 = threadIdx.x * TX;
    const int i0 = x0 >> 1;
    const int y  = blockIdx.x * blockDim.y + threadIdx.y;
    const int z  = blockIdx.y;

    float acc[CG][TX];
#pragma unroll
    for (int g = 0; g < CG; g++)
#pragma unroll
        for (int t = 0; t < TX; t++) acc[g][t] = 0.f;

    for (int c0 = 0; c0 < Cin; c0 += 32) {
        const int chunk = (Cin - c0 < 32) ? (Cin - c0) : 32;
        __syncthreads();
        for (int i = tid; i < CG * chunk * 27; i += nthr) {
            const int g   = i / (chunk * 27);
            const int rem = i - g * chunk * 27;
            sw[i] = wt[((size_t)(cb + g) * Cin + c0) * 27 + rem];
        }
        __syncthreads();

        for (int cl = 0; cl < chunk; cl++) {
            const float* inc = in + (size_t)(c0 + cl) * Di * Hi * Wi;
#pragma unroll
            for (int kd = 0; kd < 3; kd++) {
                const int dz = z - 1 + kd;
                if (dz < 0 || (dz & 1)) continue;
                const int iz = dz >> 1;
                if (iz >= Di) continue;
#pragma unroll
                for (int kh = 0; kh < 3; kh++) {
                    const int dy = y - 1 + kh;
                    if (dy < 0 || (dy & 1)) continue;
                    const int iy = dy >> 1;
                    if (iy >= Hi) continue;
                    const float* row = inc + ((size_t)iz * Hi + iy) * Wi;
                    float r[TX / 2 + 1];
#pragma unroll
                    for (int m = 0; m < TX / 2 + 1; m++) {
                        const int ix = i0 + m;
                        r[m] = (ix < Wi) ? row[ix] : 0.f;
                    }
                    const float* swp = sw + cl * 27 + kd * 9 + kh * 3;
#pragma unroll
                    for (int g = 0; g < CG; g++) {
                        const float wv0 = swp[g * chunk * 27 + 0];
                        const float wv1 = swp[g * chunk * 27 + 1];
                        const float wv2 = swp[g * chunk * 27 + 2];
#pragma unroll
                        for (int e = 0; e < TX / 2; e++) {
                            acc[g][2 * e]     += r[e] * wv1;
                            acc[g][2 * e + 1] += r[e] * wv0 + r[e + 1] * wv2;
                        }
                    }
                }
            }
        }
    }

#pragma unroll
    for (int g = 0; g < CG; g++) {
        float* orow = out + (((size_t)(cb + g) * Do + z) * Ho + y) * Wo + x0;
#pragma unroll
        for (int t = 0; t < TX; t++) orow[t] = acc[g][t];
    }
}

// ---------------------------------------------------------------------------
// BatchNorm (training-mode batch stats) + ReLU, deterministic two-stage.
// ---------------------------------------------------------------------------
__global__ void bn_stats_partial(const float* __restrict__ x,
                                 double2* __restrict__ part, int V) {
    const int c = blockIdx.y, p = blockIdx.x, P = gridDim.x;
    const float* d = x + (size_t)c * V;
    const long long start = (long long)p * V / P;
    const long long end   = (long long)(p + 1) * V / P;
    double s = 0.0, q = 0.0;
    for (long long i = start + threadIdx.x; i < end; i += blockDim.x) {
        const double v = d[i];
        s += v;
        q = fma(v, v, q);
    }
    __shared__ double ss[256], sq[256];
    ss[threadIdx.x] = s; sq[threadIdx.x] = q;
    __syncthreads();
    for (int o = 128; o > 0; o >>= 1) {
        if (threadIdx.x < o) {
            ss[threadIdx.x] += ss[threadIdx.x + o];
            sq[threadIdx.x] += sq[threadIdx.x + o];
        }
        __syncthreads();
    }
    if (threadIdx.x == 0) part[c * P + p] = make_double2(ss[0], sq[0]);
}

__global__ void bn_stats_final(const double2* __restrict__ part,
                               float2* __restrict__ mstd, int P, int V, float eps) {
    const int c = blockIdx.x;
    __shared__ double ss[64], sq[64];
    const double2 pp = part[c * P + threadIdx.x];
    ss[threadIdx.x] = pp.x; sq[threadIdx.x] = pp.y;
    __syncthreads();
    for (int o = 32; o > 0; o >>= 1) {
        if (threadIdx.x < o) {
            ss[threadIdx.x] += ss[threadIdx.x + o];
            sq[threadIdx.x] += sq[threadIdx.x + o];
        }
        __syncthreads();
    }
    if (threadIdx.x == 0) {
        const double mean = ss[0] / V;
        const double var  = sq[0] / V - mean * mean;
        mstd[c] = make_float2((float)mean, (float)(1.0 / sqrt(var + (double)eps)));
    }
}

__global__ void bn_apply(float* __restrict__ x,
                         const float2* __restrict__ mstd,
                         const float* __restrict__ gam,
                         const float* __restrict__ bet, int V) {
    const int c = blockIdx.y;
    const size_t i = (size_t)c * V + (size_t)blockIdx.x * blockDim.x + threadIdx.x;
    const float2 ms = mstd[c];
    const float v = (x[i] - ms.x) * ms.y * gam[c] + bet[c];
    x[i] = v > 0.f ? v : 0.f;
}

// ---------------------------------------------------------------------------
// Host orchestration
// ---------------------------------------------------------------------------
static void run_bn(float* buf, int C, int V, const float* g, const float* b,
                   double2* part, float2* mstd) {
    bn_stats_partial<<<dim3(64, C), 256>>>(buf, part, V);
    bn_stats_final<<<C, 64>>>(part, mstd, 64, V, 1e-5f);
    bn_apply<<<dim3(V / 256, C), 256>>>(buf, mstd, g, b, V);
}

extern "C" void kernel_launch(void* const* d_in, const int* in_sizes, int n_in,
                              void* d_out, int out_size) {
    (void)in_sizes; (void)n_in; (void)out_size;

    const float* x     = (const float*)d_in[0];
    const float* w0    = (const float*)d_in[1];
    const float* g0    = (const float*)d_in[2];
    const float* b0    = (const float*)d_in[3];
    const float* w1    = (const float*)d_in[4];
    const float* g1    = (const float*)d_in[5];
    const float* b1    = (const float*)d_in[6];
    const float* w2    = (const float*)d_in[7];
    const float* g2    = (const float*)d_in[8];
    const float* b2    = (const float*)d_in[9];
    const float* w3    = (const float*)d_in[10];
    const float* g3    = (const float*)d_in[11];
    const float* b3    = (const float*)d_in[12];
    const float* wt3   = (const float*)d_in[13];
    const float* gt3   = (const float*)d_in[14];
    const float* bt3   = (const float*)d_in[15];
    const float* wt2   = (const float*)d_in[16];
    const float* gt2   = (const float*)d_in[17];
    const float* bt2   = (const float*)d_in[18];
    const float* wt1   = (const float*)d_in[19];
    const float* gt1   = (const float*)d_in[20];
    const float* bt1   = (const float*)d_in[21];
    const float* w_out = (const float*)d_in[22];

    float *cat0, *cat1, *cat2, *s8;
    double2* part;
    float2* mstd;
    cudaGetSymbolAddress((void**)&cat0, g_cat0);
    cudaGetSymbolAddress((void**)&cat1, g_cat1);
    cudaGetSymbolAddress((void**)&cat2, g_cat2);
    cudaGetSymbolAddress((void**)&s8,   g_s8);
    cudaGetSymbolAddress((void**)&part, g_part);
    cudaGetSymbolAddress((void**)&mstd, g_mstd);

    float* s1 = cat0 + (size_t)24 * V0_;   // channels 24..31 of cat0
    float* s2 = cat1 + (size_t)32 * V1_;   // channels 32..47 of cat1
    float* s4 = cat2 + (size_t)32 * V2_;   // channels 32..63 of cat2

    // ---- encoder ----
    // conv0: 8->8, 128^3, stride 1
    conv_s1_kernel<8, 8><<<dim3(16, 128, 1), dim3(16, 8), 8 * 8 * 27 * 4>>>(
        x, w0, s1, 8, 128, 128, 128);
    run_bn(s1, 8, V0_, g0, b0, part, mstd);

    // conv1: 8->16, stride 2 -> 64^3
    conv_s2_kernel<16><<<dim3(16, 64, 1), dim3(64, 4), 16 * 8 * 27 * 4>>>(
        s1, w1, s2, 8, 128, 128, 128, 64, 64, 64);
    run_bn(s2, 16, V1_, g1, b1, part, mstd);

    // conv2: 16->32, stride 2 -> 32^3
    conv_s2_kernel<16><<<dim3(4, 32, 2), dim3(32, 8), 16 * 16 * 27 * 4>>>(
        s2, w2, s4, 16, 64, 64, 64, 32, 32, 32);
    run_bn(s4, 32, V2_, g2, b2, part, mstd);

    // conv3: 32->64, stride 2 -> 16^3
    conv_s2_kernel<8><<<dim3(1, 16, 8), dim3(16, 16), 8 * 32 * 27 * 4>>>(
        s4, w3, s8, 32, 32, 32, 32, 16, 16, 16);
    run_bn(s8, 64, V3_, g3, b3, part, mstd);

    // ---- decoder ----
    // tconv3: 64->32, 16^3 -> 32^3, into cat2 channels 0..31
    tconv_kernel<8, 8><<<dim3(1, 32, 4), dim3(4, 32), 8 * 32 * 27 * 4>>>(
        s8, wt3, cat2, 64, 16, 16, 16);
    run_bn(cat2, 32, V2_, gt3, bt3, part, mstd);

    // tconv2: 64->32, 32^3 -> 64^3, into cat1 channels 0..31
    tconv_kernel<8, 8><<<dim3(4, 64, 4), dim3(8, 16), 8 * 32 * 27 * 4>>>(
        cat2, wt2, cat1, 64, 32, 32, 32);
    run_bn(cat1, 32, V1_, gt2, bt2, part, mstd);

    // tconv1: 48->24, 64^3 -> 128^3, into cat0 channels 0..23
    tconv_kernel<8, 8><<<dim3(16, 128, 3), dim3(16, 8), 8 * 32 * 27 * 4>>>(
        cat1, wt1, cat0, 48, 64, 64, 64);
    run_bn(cat0, 24, V0_, gt1, bt1, part, mstd);

    // conv_out: 32->2, 128^3, stride 1 (no BN/ReLU)
    conv_s1_kernel<2, 8><<<dim3(16, 128, 1), dim3(16, 8), 2 * 32 * 27 * 4>>>(
        cat0, w_out, (float*)d_out, 32, 128, 128, 128);
}

// round 2
// speedup vs baseline: 1.5848x; 1.5848x over previous
#include <cuda_runtime.h>
#include <cstdint>
#include <math.h>

// ---------------------------------------------------------------------------
// UNet4LMCD: 4-level 3D U-Net, fp32 direct convolutions, round 2.
//  - float4-vectorized input row loads in all conv kernels
//  - conv_s2 rewritten with x-register tiling (TX outputs/thread)
//  - BN statistics fused into conv epilogues (deterministic block partials)
//  - vectorized BN apply
// Encoder outputs are written straight into their channel slice of the
// decoder concat buffers so the "concatenate" ops are free.
// ---------------------------------------------------------------------------

#define V0_ (128*128*128)
#define V1_ (64*64*64)
#define V2_ (32*32*32)
#define V3_ (16*16*16)
#define PMAX_ 2048   // max per-channel partial count (= max gridDim.x*gridDim.y)

__device__ float   g_s8  [64 * V3_];          // 1 MB   encoder level 8
__device__ float   g_cat2[64 * V2_];          // 8.4 MB [tconv3 out (32) | s4 (32)]
__device__ float   g_cat1[48 * V1_];          // 50 MB  [tconv2 out (32) | s2 (16)]
__device__ float   g_cat0[32u * V0_];         // 268 MB [tconv1 out (24) | s1 (8)]
__device__ double2 g_part[64 * PMAX_];        // BN per-block partial (sum, sumsq)
__device__ float2  g_mstd[64];                // BN (mean, inv_std)

// ---------------------------------------------------------------------------
// Fused BN-stats epilogue: block-wide reduction of the register accumulators,
// one deterministic double2 partial per (channel, block).
// ---------------------------------------------------------------------------
template <int CG, int TX>
__device__ __forceinline__ void stats_epilogue(const float acc[CG][TX],
                                               double2* __restrict__ part,
                                               int cb, int tid, int nthr) {
    float s[CG], q[CG];
#pragma unroll
    for (int g = 0; g < CG; g++) {
        float ss = 0.f, qq = 0.f;
#pragma unroll
        for (int t = 0; t < TX; t++) {
            ss += acc[g][t];
            qq = fmaf(acc[g][t], acc[g][t], qq);
        }
        s[g] = ss; q[g] = qq;
    }
#pragma unroll
    for (int o = 16; o > 0; o >>= 1) {
#pragma unroll
        for (int g = 0; g < CG; g++) {
            s[g] += __shfl_down_sync(0xffffffffu, s[g], o);
            q[g] += __shfl_down_sync(0xffffffffu, q[g], o);
        }
    }
    __shared__ float2 red[CG][8];
    const int wid = tid >> 5, lane = tid & 31;
    if (lane == 0) {
#pragma unroll
        for (int g = 0; g < CG; g++) red[g][wid] = make_float2(s[g], q[g]);
    }
    __syncthreads();
    const int nw = nthr >> 5;
    if (tid < CG) {
        double ds = 0.0, dq = 0.0;
        for (int w = 0; w < nw; w++) {
            ds += (double)red[tid][w].x;
            dq += (double)red[tid][w].y;
        }
        const int pidx = blockIdx.x + gridDim.x * blockIdx.y;
        part[(size_t)(cb + tid) * PMAX_ + pidx] = make_double2(ds, dq);
    }
}

// ---------------------------------------------------------------------------
// Stride-1 3x3x3 conv, register tile CG x 8. float4 row loads.
// ---------------------------------------------------------------------------
template <int CG, int TX, bool STATS>
__global__ void __launch_bounds__(128) conv_s1_kernel(
        const float* __restrict__ in, const float* __restrict__ wt,
        float* __restrict__ out, double2* __restrict__ part,
        int Cin, int D, int H, int W) {
    static_assert(TX == 8, "conv_s1 vector path needs TX==8");
    extern __shared__ float sw[];
    const int cb   = blockIdx.z * CG;
    const int tid  = threadIdx.y * blockDim.x + threadIdx.x;
    const int nthr = blockDim.x * blockDim.y;
    for (int i = tid; i < CG * Cin * 27; i += nthr)
        sw[i] = wt[(size_t)cb * Cin * 27 + i];
    __syncthreads();

    const int x0 = threadIdx.x * TX;
    const int y  = blockIdx.x * blockDim.y + threadIdx.y;
    const int z  = blockIdx.y;

    float acc[CG][TX];
#pragma unroll
    for (int g = 0; g < CG; g++)
#pragma unroll
        for (int t = 0; t < TX; t++) acc[g][t] = 0.f;

    for (int ci = 0; ci < Cin; ci++) {
        const float* inc = in + (size_t)ci * D * H * W;
#pragma unroll
        for (int kd = 0; kd < 3; kd++) {
            const int iz = z + kd - 1;
            if (iz < 0 || iz >= D) continue;
#pragma unroll
            for (int kh = 0; kh < 3; kh++) {
                const int iy = y + kh - 1;
                if (iy < 0 || iy >= H) continue;
                const float* row = inc + ((size_t)iz * H + iy) * W;
                float r[TX + 2];
                r[0] = (x0 > 0) ? row[x0 - 1] : 0.f;
                const float4 v0 = *reinterpret_cast<const float4*>(row + x0);
                const float4 v1 = *reinterpret_cast<const float4*>(row + x0 + 4);
                r[1] = v0.x; r[2] = v0.y; r[3] = v0.z; r[4] = v0.w;
                r[5] = v1.x; r[6] = v1.y; r[7] = v1.z; r[8] = v1.w;
                r[9] = (x0 + TX < W) ? row[x0 + TX] : 0.f;
                const float* swp = sw + ci * 27 + kd * 9 + kh * 3;
#pragma unroll
                for (int g = 0; g < CG; g++) {
                    const float wv0 = swp[g * Cin * 27 + 0];
                    const float wv1 = swp[g * Cin * 27 + 1];
                    const float wv2 = swp[g * Cin * 27 + 2];
#pragma unroll
                    for (int t = 0; t < TX; t++)
                        acc[g][t] = fmaf(r[t], wv0,
                                    fmaf(r[t + 1], wv1,
                                    fmaf(r[t + 2], wv2, acc[g][t])));
                }
            }
        }
    }

#pragma unroll
    for (int g = 0; g < CG; g++) {
        float* orow = out + (((size_t)(cb + g) * D + z) * H + y) * W + x0;
#pragma unroll
        for (int t = 0; t < TX; t += 4)
            *reinterpret_cast<float4*>(orow + t) =
                make_float4(acc[g][t], acc[g][t + 1], acc[g][t + 2], acc[g][t + 3]);
    }
    if (STATS) stats_epilogue<CG, TX>(acc, part, cb, tid, nthr);
}

// ---------------------------------------------------------------------------
// Stride-2 3x3x3 conv, register tile CG x TX(=4). float4 row loads.
// ---------------------------------------------------------------------------
template <int CG, int TX, bool STATS>
__global__ void conv_s2_kernel(
        const float* __restrict__ in, const float* __restrict__ wt,
        float* __restrict__ out, double2* __restrict__ part,
        int Cin, int Di, int Hi, int Wi, int Do, int Ho, int Wo) {
    static_assert(TX == 4, "conv_s2 vector path needs TX==4");
    extern __shared__ float sw[];
    const int cb   = blockIdx.z * CG;
    const int tid  = threadIdx.y * blockDim.x + threadIdx.x;
    const int nthr = blockDim.x * blockDim.y;
    for (int i = tid; i < CG * Cin * 27; i += nthr)
        sw[i] = wt[(size_t)cb * Cin * 27 + i];
    __syncthreads();

    const int x0 = threadIdx.x * TX;
    const int bx = 2 * x0;                       // multiple of 8
    const int y  = blockIdx.x * blockDim.y + threadIdx.y;
    const int z  = blockIdx.y;

    float acc[CG][TX];
#pragma unroll
    for (int g = 0; g < CG; g++)
#pragma unroll
        for (int t = 0; t < TX; t++) acc[g][t] = 0.f;

    for (int ci = 0; ci < Cin; ci++) {
        const float* inc = in + (size_t)ci * Di * Hi * Wi;
#pragma unroll
        for (int kd = 0; kd < 3; kd++) {
            const int iz = 2 * z + kd - 1;
            if (iz < 0 || iz >= Di) continue;
#pragma unroll
            for (int kh = 0; kh < 3; kh++) {
                const int iy = 2 * y + kh - 1;
                if (iy < 0 || iy >= Hi) continue;
                const float* row = inc + ((size_t)iz * Hi + iy) * Wi;
                float rr[2 * TX + 2];             // covers ix = bx-1 .. bx+2*TX
                rr[0] = (bx > 0) ? row[bx - 1] : 0.f;
                const float4 v0 = *reinterpret_cast<const float4*>(row + bx);
                const float4 v1 = *reinterpret_cast<const float4*>(row + bx + 4);
                rr[1] = v0.x; rr[2] = v0.y; rr[3] = v0.z; rr[4] = v0.w;
                rr[5] = v1.x; rr[6] = v1.y; rr[7] = v1.z; rr[8] = v1.w;
                rr[2 * TX + 1] = (bx + 2 * TX < Wi) ? row[bx + 2 * TX] : 0.f;
                const float* swp = sw + ci * 27 + kd * 9 + kh * 3;
#pragma unroll
                for (int g = 0; g < CG; g++) {
                    const float wv0 = swp[g * Cin * 27 + 0];
                    const float wv1 = swp[g * Cin * 27 + 1];
                    const float wv2 = swp[g * Cin * 27 + 2];
#pragma unroll
                    for (int t = 0; t < TX; t++)
                        acc[g][t] = fmaf(rr[2 * t], wv0,
                                    fmaf(rr[2 * t + 1], wv1,
                                    fmaf(rr[2 * t + 2], wv2, acc[g][t])));
                }
            }
        }
    }

#pragma unroll
    for (int g = 0; g < CG; g++) {
        float* orow = out + (((size_t)(cb + g) * Do + z) * Ho + y) * Wo + x0;
        *reinterpret_cast<float4*>(orow) =
            make_float4(acc[g][0], acc[g][1], acc[g][2], acc[g][3]);
    }
    if (STATS) stats_epilogue<CG, TX>(acc, part, cb, tid, nthr);
}

// ---------------------------------------------------------------------------
// Stride-2 transposed 3x3x3 conv (output-gather, parity taps). CG x 8 tile.
// ---------------------------------------------------------------------------
template <int CG, int TX, bool STATS>
__global__ void tconv_kernel(
        const float* __restrict__ in, const float* __restrict__ wt,
        float* __restrict__ out, double2* __restrict__ part,
        int Cin, int Di, int Hi, int Wi) {
    static_assert(TX == 8, "tconv vector path needs TX==8");
    const int Do = 2 * Di, Ho = 2 * Hi, Wo = 2 * Wi;
    extern __shared__ float sw[];
    const int cb   = blockIdx.z * CG;
    const int tid  = threadIdx.y * blockDim.x + threadIdx.x;
    const int nthr = blockDim.x * blockDim.y;

    const int x0 = threadIdx.x * TX;
    const int i0 = x0 >> 1;                       // multiple of 4
    const int y  = blockIdx.x * blockDim.y + threadIdx.y;
    const int z  = blockIdx.y;

    float acc[CG][TX];
#pragma unroll
    for (int g = 0; g < CG; g++)
#pragma unroll
        for (int t = 0; t < TX; t++) acc[g][t] = 0.f;

    for (int c0 = 0; c0 < Cin; c0 += 32) {
        const int chunk = (Cin - c0 < 32) ? (Cin - c0) : 32;
        __syncthreads();
        for (int i = tid; i < CG * chunk * 27; i += nthr) {
            const int g   = i / (chunk * 27);
            const int rem = i - g * chunk * 27;
            sw[i] = wt[((size_t)(cb + g) * Cin + c0) * 27 + rem];
        }
        __syncthreads();

        for (int cl = 0; cl < chunk; cl++) {
            const float* inc = in + (size_t)(c0 + cl) * Di * Hi * Wi;
#pragma unroll
            for (int kd = 0; kd < 3; kd++) {
                const int dz = z - 1 + kd;
                if (dz < 0 || (dz & 1)) continue;
                const int iz = dz >> 1;
                if (iz >= Di) continue;
#pragma unroll
                for (int kh = 0; kh < 3; kh++) {
                    const int dy = y - 1 + kh;
                    if (dy < 0 || (dy & 1)) continue;
                    const int iy = dy >> 1;
                    if (iy >= Hi) continue;
                    const float* row = inc + ((size_t)iz * Hi + iy) * Wi;
                    float r[TX / 2 + 1];
                    const float4 v0 = *reinterpret_cast<const float4*>(row + i0);
                    r[0] = v0.x; r[1] = v0.y; r[2] = v0.z; r[3] = v0.w;
                    r[4] = (i0 + 4 < Wi) ? row[i0 + 4] : 0.f;
                    const float* swp = sw + cl * 27 + kd * 9 + kh * 3;
#pragma unroll
                    for (int g = 0; g < CG; g++) {
                        const float wv0 = swp[g * chunk * 27 + 0];
                        const float wv1 = swp[g * chunk * 27 + 1];
                        const float wv2 = swp[g * chunk * 27 + 2];
#pragma unroll
                        for (int e = 0; e < TX / 2; e++) {
                            acc[g][2 * e]     = fmaf(r[e], wv1, acc[g][2 * e]);
                            acc[g][2 * e + 1] = fmaf(r[e], wv0,
                                                fmaf(r[e + 1], wv2, acc[g][2 * e + 1]));
                        }
                    }
                }
            }
        }
    }

#pragma unroll
    for (int g = 0; g < CG; g++) {
        float* orow = out + (((size_t)(cb + g) * Do + z) * Ho + y) * Wo + x0;
#pragma unroll
        for (int t = 0; t < TX; t += 4)
            *reinterpret_cast<float4*>(orow + t) =
                make_float4(acc[g][t], acc[g][t + 1], acc[g][t + 2], acc[g][t + 3]);
    }
    if (STATS) stats_epilogue<CG, TX>(acc, part, cb, tid, nthr);
}

// ---------------------------------------------------------------------------
// BN finalize: reduce P per-block partials per channel -> (mean, inv_std).
// ---------------------------------------------------------------------------
__global__ void bn_stats_final(const double2* __restrict__ part,
                               float2* __restrict__ mstd,
                               int P, int V, float eps) {
    const int c = blockIdx.x;
    double s = 0.0, q = 0.0;
    for (int i = threadIdx.x; i < P; i += 256) {
        const double2 pp = part[(size_t)c * PMAX_ + i];
        s += pp.x; q += pp.y;
    }
    __shared__ double ss[256], sq[256];
    ss[threadIdx.x] = s; sq[threadIdx.x] = q;
    __syncthreads();
    for (int o = 128; o > 0; o >>= 1) {
        if (threadIdx.x < o) {
            ss[threadIdx.x] += ss[threadIdx.x + o];
            sq[threadIdx.x] += sq[threadIdx.x + o];
        }
        __syncthreads();
    }
    if (threadIdx.x == 0) {
        const double mean = ss[0] / V;
        const double var  = sq[0] / V - mean * mean;
        mstd[c] = make_float2((float)mean, (float)(1.0 / sqrt(var + (double)eps)));
    }
}

// ---------------------------------------------------------------------------
// BN apply + ReLU, vectorized.
// ---------------------------------------------------------------------------
__global__ void bn_apply(float4* __restrict__ x,
                         const float2* __restrict__ mstd,
                         const float* __restrict__ gam,
                         const float* __restrict__ bet, int Vq) {
    const int c = blockIdx.y;
    const size_t i = (size_t)c * Vq + (size_t)blockIdx.x * blockDim.x + threadIdx.x;
    const float2 ms = mstd[c];
    const float a = ms.y * gam[c];
    const float b = fmaf(-ms.x, a, bet[c]);
    float4 v = x[i];
    v.x = fmaxf(fmaf(v.x, a, b), 0.f);
    v.y = fmaxf(fmaf(v.y, a, b), 0.f);
    v.z = fmaxf(fmaf(v.z, a, b), 0.f);
    v.w = fmaxf(fmaf(v.w, a, b), 0.f);
    x[i] = v;
}

// ---------------------------------------------------------------------------
// Host orchestration
// ---------------------------------------------------------------------------
static void run_bn(float* buf, int C, int V, int P, const float* g, const float* b,
                   double2* part, float2* mstd) {
    bn_stats_final<<<C, 256>>>(part, mstd, P, V, 1e-5f);
    const int vq = V / 4;
    const int bs = (vq >= 256) ? 256 : vq;
    bn_apply<<<dim3(vq / bs, C), bs>>>((float4*)buf, mstd, g, b, vq);
}

extern "C" void kernel_launch(void* const* d_in, const int* in_sizes, int n_in,
                              void* d_out, int out_size) {
    (void)in_sizes; (void)n_in; (void)out_size;

    const float* x     = (const float*)d_in[0];
    const float* w0    = (const float*)d_in[1];
    const float* g0    = (const float*)d_in[2];
    const float* b0    = (const float*)d_in[3];
    const float* w1    = (const float*)d_in[4];
    const float* g1    = (const float*)d_in[5];
    const float* b1    = (const float*)d_in[6];
    const float* w2    = (const float*)d_in[7];
    const float* g2    = (const float*)d_in[8];
    const float* b2    = (const float*)d_in[9];
    const float* w3    = (const float*)d_in[10];
    const float* g3    = (const float*)d_in[11];
    const float* b3    = (const float*)d_in[12];
    const float* wt3   = (const float*)d_in[13];
    const float* gt3   = (const float*)d_in[14];
    const float* bt3   = (const float*)d_in[15];
    const float* wt2   = (const float*)d_in[16];
    const float* gt2   = (const float*)d_in[17];
    const float* bt2   = (const float*)d_in[18];
    const float* wt1   = (const float*)d_in[19];
    const float* gt1   = (const float*)d_in[20];
    const float* bt1   = (const float*)d_in[21];
    const float* w_out = (const float*)d_in[22];

    float *cat0, *cat1, *cat2, *s8;
    double2* part;
    float2* mstd;
    cudaGetSymbolAddress((void**)&cat0, g_cat0);
    cudaGetSymbolAddress((void**)&cat1, g_cat1);
    cudaGetSymbolAddress((void**)&cat2, g_cat2);
    cudaGetSymbolAddress((void**)&s8,   g_s8);
    cudaGetSymbolAddress((void**)&part, g_part);
    cudaGetSymbolAddress((void**)&mstd, g_mstd);

    float* s1 = cat0 + (size_t)24 * V0_;   // channels 24..31 of cat0
    float* s2 = cat1 + (size_t)32 * V1_;   // channels 32..47 of cat1
    float* s4 = cat2 + (size_t)32 * V2_;   // channels 32..63 of cat2

    // ---- encoder ----
    // conv0: 8->8, 128^3, stride 1
    conv_s1_kernel<8, 8, true><<<dim3(16, 128, 1), dim3(16, 8), 8 * 8 * 27 * 4>>>(
        x, w0, s1, part, 8, 128, 128, 128);
    run_bn(s1, 8, V0_, 16 * 128, g0, b0, part, mstd);

    // conv1: 8->16, stride 2 -> 64^3
    conv_s2_kernel<16, 4, true><<<dim3(8, 64, 1), dim3(16, 8), 16 * 8 * 27 * 4>>>(
        s1, w1, s2, part, 8, 128, 128, 128, 64, 64, 64);
    run_bn(s2, 16, V1_, 8 * 64, g1, b1, part, mstd);

    // conv2: 16->32, stride 2 -> 32^3
    conv_s2_kernel<16, 4, true><<<dim3(2, 32, 2), dim3(8, 16), 16 * 16 * 27 * 4>>>(
        s2, w2, s4, part, 16, 64, 64, 64, 32, 32, 32);
    run_bn(s4, 32, V2_, 2 * 32, g2, b2, part, mstd);

    // conv3: 32->64, stride 2 -> 16^3
    conv_s2_kernel<8, 4, true><<<dim3(1, 16, 8), dim3(4, 16), 8 * 32 * 27 * 4>>>(
        s4, w3, s8, part, 32, 32, 32, 32, 16, 16, 16);
    run_bn(s8, 64, V3_, 1 * 16, g3, b3, part, mstd);

    // ---- decoder ----
    // tconv3: 64->32, 16^3 -> 32^3, into cat2 channels 0..31
    tconv_kernel<8, 8, true><<<dim3(1, 32, 4), dim3(4, 32), 8 * 32 * 27 * 4>>>(
        s8, wt3, cat2, part, 64, 16, 16, 16);
    run_bn(cat2, 32, V2_, 1 * 32, gt3, bt3, part, mstd);

    // tconv2: 64->32, 32^3 -> 64^3, into cat1 channels 0..31
    tconv_kernel<8, 8, true><<<dim3(4, 64, 4), dim3(8, 16), 8 * 32 * 27 * 4>>>(
        cat2, wt2, cat1, part, 64, 32, 32, 32);
    run_bn(cat1, 32, V1_, 4 * 64, gt2, bt2, part, mstd);

    // tconv1: 48->24, 64^3 -> 128^3, into cat0 channels 0..23
    tconv_kernel<8, 8, true><<<dim3(16, 128, 3), dim3(16, 8), 8 * 32 * 27 * 4>>>(
        cat1, wt1, cat0, part, 48, 64, 64, 64);
    run_bn(cat0, 24, V0_, 16 * 128, gt1, bt1, part, mstd);

    // conv_out: 32->2, 128^3, stride 1 (no BN/ReLU)
    conv_s1_kernel<2, 8, false><<<dim3(16, 128, 1), dim3(16, 8), 2 * 32 * 27 * 4>>>(
        cat0, w_out, (float*)d_out, nullptr, 32, 128, 128, 128);
}

// round 3
// speedup vs baseline: 2.0534x; 1.2957x over previous
#include <cuda_runtime.h>
#include <cstdint>
#include <math.h>

// ---------------------------------------------------------------------------
// UNet4LMCD round 3: fp32 direct conv, issue-efficiency pass.
//  - tconv: y-pair register tiling -> zero warp divergence + 1.5x fewer loads
//  - conv_s1: TZ z-tiling (used for conv_out) -> 1.5x fewer loads, 2x ILP
//  - conv_s2: CG=8 everywhere -> more blocks, ~2x occupancy
//  - BN stats fused in conv epilogues; vectorized BN apply
// ---------------------------------------------------------------------------

#define V0_ (128*128*128)
#define V1_ (64*64*64)
#define V2_ (32*32*32)
#define V3_ (16*16*16)
#define PMAX_ 2048

__device__ float   g_s8  [64 * V3_];
__device__ float   g_cat2[64 * V2_];          // [tconv3 out (32) | s4 (32)]
__device__ float   g_cat1[48 * V1_];          // [tconv2 out (32) | s2 (16)]
__device__ float   g_cat0[32u * V0_];         // [tconv1 out (24) | s1 (8)]
__device__ double2 g_part[64 * PMAX_];
__device__ float2  g_mstd[64];

// ---------------------------------------------------------------------------
// Fused BN-stats epilogue over flattened accumulators acc[CG][NT].
// ---------------------------------------------------------------------------
template <int CG, int NT>
__device__ __forceinline__ void stats_epilogue(const float (*acc)[NT],
                                               double2* __restrict__ part,
                                               int cb, int tid, int nthr) {
    float s[CG], q[CG];
#pragma unroll
    for (int g = 0; g < CG; g++) {
        float ss = 0.f, qq = 0.f;
#pragma unroll
        for (int t = 0; t < NT; t++) {
            ss += acc[g][t];
            qq = fmaf(acc[g][t], acc[g][t], qq);
        }
        s[g] = ss; q[g] = qq;
    }
#pragma unroll
    for (int o = 16; o > 0; o >>= 1) {
#pragma unroll
        for (int g = 0; g < CG; g++) {
            s[g] += __shfl_down_sync(0xffffffffu, s[g], o);
            q[g] += __shfl_down_sync(0xffffffffu, q[g], o);
        }
    }
    __shared__ float2 red[CG][8];
    const int wid = tid >> 5, lane = tid & 31;
    if (lane == 0) {
#pragma unroll
        for (int g = 0; g < CG; g++) red[g][wid] = make_float2(s[g], q[g]);
    }
    __syncthreads();
    const int nw = nthr >> 5;
    if (tid < CG) {
        double ds = 0.0, dq = 0.0;
        for (int w = 0; w < nw; w++) {
            ds += (double)red[tid][w].x;
            dq += (double)red[tid][w].y;
        }
        const int pidx = blockIdx.x + gridDim.x * blockIdx.y;
        part[(size_t)(cb + tid) * PMAX_ + pidx] = make_double2(ds, dq);
    }
}

// ---------------------------------------------------------------------------
// Stride-1 3x3x3 conv: CG out-channels x TZ z x TX(=8) x per thread.
// Input planes are loaded once and applied to every z-output they overlap.
// ---------------------------------------------------------------------------
template <int CG, int TZ, int TX, bool STATS>
__global__ void __launch_bounds__(128) conv_s1_kernel(
        const float* __restrict__ in, const float* __restrict__ wt,
        float* __restrict__ out, double2* __restrict__ part,
        int Cin, int D, int H, int W) {
    static_assert(TX == 8, "conv_s1 needs TX==8");
    extern __shared__ float sw[];
    const int cb   = blockIdx.z * CG;
    const int tid  = threadIdx.y * blockDim.x + threadIdx.x;
    const int nthr = blockDim.x * blockDim.y;
    for (int i = tid; i < CG * Cin * 27; i += nthr)
        sw[i] = wt[(size_t)cb * Cin * 27 + i];
    __syncthreads();

    const int x0 = threadIdx.x * TX;
    const int y  = blockIdx.x * blockDim.y + threadIdx.y;
    const int z0 = blockIdx.y * TZ;

    float acc[CG][TZ][TX];
#pragma unroll
    for (int g = 0; g < CG; g++)
#pragma unroll
        for (int zz = 0; zz < TZ; zz++)
#pragma unroll
            for (int t = 0; t < TX; t++) acc[g][zz][t] = 0.f;

    for (int ci = 0; ci < Cin; ci++) {
        const float* inc = in + (size_t)ci * D * H * W;
#pragma unroll
        for (int pz = 0; pz < TZ + 2; pz++) {
            const int iz = z0 - 1 + pz;
            if (iz < 0 || iz >= D) continue;
#pragma unroll
            for (int kh = 0; kh < 3; kh++) {
                const int iy = y + kh - 1;
                if (iy < 0 || iy >= H) continue;
                const float* row = inc + ((size_t)iz * H + iy) * W;
                float r[TX + 2];
                r[0] = (x0 > 0) ? row[x0 - 1] : 0.f;
                const float4 v0 = *reinterpret_cast<const float4*>(row + x0);
                const float4 v1 = *reinterpret_cast<const float4*>(row + x0 + 4);
                r[1] = v0.x; r[2] = v0.y; r[3] = v0.z; r[4] = v0.w;
                r[5] = v1.x; r[6] = v1.y; r[7] = v1.z; r[8] = v1.w;
                r[9] = (x0 + TX < W) ? row[x0 + TX] : 0.f;
#pragma unroll
                for (int zz = 0; zz < TZ; zz++) {
                    const int kd = iz - (z0 + zz) + 1;
                    if (kd < 0 || kd > 2) continue;
                    const float* swp = sw + ci * 27 + kd * 9 + kh * 3;
#pragma unroll
                    for (int g = 0; g < CG; g++) {
                        const float wv0 = swp[g * Cin * 27 + 0];
                        const float wv1 = swp[g * Cin * 27 + 1];
                        const float wv2 = swp[g * Cin * 27 + 2];
#pragma unroll
                        for (int t = 0; t < TX; t++)
                            acc[g][zz][t] = fmaf(r[t], wv0,
                                            fmaf(r[t + 1], wv1,
                                            fmaf(r[t + 2], wv2, acc[g][zz][t])));
                    }
                }
            }
        }
    }

#pragma unroll
    for (int g = 0; g < CG; g++)
#pragma unroll
        for (int zz = 0; zz < TZ; zz++) {
            float* orow = out + (((size_t)(cb + g) * D + z0 + zz) * H + y) * W + x0;
#pragma unroll
            for (int t = 0; t < TX; t += 4)
                *reinterpret_cast<float4*>(orow + t) =
                    make_float4(acc[g][zz][t], acc[g][zz][t + 1],
                                acc[g][zz][t + 2], acc[g][zz][t + 3]);
        }
    if (STATS)
        stats_epilogue<CG, TZ * TX>(
            reinterpret_cast<const float(*)[TZ * TX]>(acc), part, cb, tid, nthr);
}

// ---------------------------------------------------------------------------
// Stride-2 3x3x3 conv, register tile CG x TX(=4). float4 row loads.
// ---------------------------------------------------------------------------
template <int CG, int TX, bool STATS>
__global__ void conv_s2_kernel(
        const float* __restrict__ in, const float* __restrict__ wt,
        float* __restrict__ out, double2* __restrict__ part,
        int Cin, int Di, int Hi, int Wi, int Do, int Ho, int Wo) {
    static_assert(TX == 4, "conv_s2 needs TX==4");
    extern __shared__ float sw[];
    const int cb   = blockIdx.z * CG;
    const int tid  = threadIdx.y * blockDim.x + threadIdx.x;
    const int nthr = blockDim.x * blockDim.y;
    for (int i = tid; i < CG * Cin * 27; i += nthr)
        sw[i] = wt[(size_t)cb * Cin * 27 + i];
    __syncthreads();

    const int x0 = threadIdx.x * TX;
    const int bx = 2 * x0;
    const int y  = blockIdx.x * blockDim.y + threadIdx.y;
    const int z  = blockIdx.y;

    float acc[CG][TX];
#pragma unroll
    for (int g = 0; g < CG; g++)
#pragma unroll
        for (int t = 0; t < TX; t++) acc[g][t] = 0.f;

    for (int ci = 0; ci < Cin; ci++) {
        const float* inc = in + (size_t)ci * Di * Hi * Wi;
#pragma unroll
        for (int kd = 0; kd < 3; kd++) {
            const int iz = 2 * z + kd - 1;
            if (iz < 0 || iz >= Di) continue;
#pragma unroll
            for (int kh = 0; kh < 3; kh++) {
                const int iy = 2 * y + kh - 1;
                if (iy < 0 || iy >= Hi) continue;
                const float* row = inc + ((size_t)iz * Hi + iy) * Wi;
                float rr[2 * TX + 2];
                rr[0] = (bx > 0) ? row[bx - 1] : 0.f;
                const float4 v0 = *reinterpret_cast<const float4*>(row + bx);
                const float4 v1 = *reinterpret_cast<const float4*>(row + bx + 4);
                rr[1] = v0.x; rr[2] = v0.y; rr[3] = v0.z; rr[4] = v0.w;
                rr[5] = v1.x; rr[6] = v1.y; rr[7] = v1.z; rr[8] = v1.w;
                rr[2 * TX + 1] = (bx + 2 * TX < Wi) ? row[bx + 2 * TX] : 0.f;
                const float* swp = sw + ci * 27 + kd * 9 + kh * 3;
#pragma unroll
                for (int g = 0; g < CG; g++) {
                    const float wv0 = swp[g * Cin * 27 + 0];
                    const float wv1 = swp[g * Cin * 27 + 1];
                    const float wv2 = swp[g * Cin * 27 + 2];
#pragma unroll
                    for (int t = 0; t < TX; t++)
                        acc[g][t] = fmaf(rr[2 * t], wv0,
                                    fmaf(rr[2 * t + 1], wv1,
                                    fmaf(rr[2 * t + 2], wv2, acc[g][t])));
                }
            }
        }
    }

#pragma unroll
    for (int g = 0; g < CG; g++) {
        float* orow = out + (((size_t)(cb + g) * Do + z) * Ho + y) * Wo + x0;
        *reinterpret_cast<float4*>(orow) =
            make_float4(acc[g][0], acc[g][1], acc[g][2], acc[g][3]);
    }
    if (STATS)
        stats_epilogue<CG, TX>(
            reinterpret_cast<const float(*)[TX]>(acc), part, cb, tid, nthr);
}

// ---------------------------------------------------------------------------
// Stride-2 transposed conv, y-PAIR register tile: each thread computes outputs
// (2*yp, 2*yp+1) x TX(=4) x-positions x CG channels. The pair shares input
// rows iy = yp, yp+1 -> uniform control flow (no parity divergence) and 1.5x
// fewer row loads. x parity handled in-register as before.
// ---------------------------------------------------------------------------
template <int CG, int TX, bool STATS>
__global__ void tconv_kernel(
        const float* __restrict__ in, const float* __restrict__ wt,
        float* __restrict__ out, double2* __restrict__ part,
        int Cin, int Di, int Hi, int Wi) {
    static_assert(TX == 4, "tconv needs TX==4");
    const int Do = 2 * Di, Ho = 2 * Hi, Wo = 2 * Wi;
    extern __shared__ float sw[];
    const int cb   = blockIdx.z * CG;
    const int tid  = threadIdx.y * blockDim.x + threadIdx.x;
    const int nthr = blockDim.x * blockDim.y;

    const int x0 = threadIdx.x * TX;
    const int i0 = x0 >> 1;                       // multiple of 2
    const int yp = blockIdx.x * blockDim.y + threadIdx.y;  // y-pair index
    const int z  = blockIdx.y;

    float acc[CG][2 * TX];                        // [even-y outputs | odd-y outputs]
#pragma unroll
    for (int g = 0; g < CG; g++)
#pragma unroll
        for (int t = 0; t < 2 * TX; t++) acc[g][t] = 0.f;

    const bool hb = (yp + 1 < Hi);
    const bool xe = (i0 + TX / 2 < Wi);

    for (int c0 = 0; c0 < Cin; c0 += 32) {
        const int chunk = (Cin - c0 < 32) ? (Cin - c0) : 32;
        __syncthreads();
        for (int i = tid; i < CG * chunk * 27; i += nthr) {
            const int g   = i / (chunk * 27);
            const int rem = i - g * chunk * 27;
            sw[i] = wt[((size_t)(cb + g) * Cin + c0) * 27 + rem];
        }
        __syncthreads();

        for (int cl = 0; cl < chunk; cl++) {
            const float* inc = in + (size_t)(c0 + cl) * Di * Hi * Wi;
#pragma unroll
            for (int kd = 0; kd < 3; kd++) {
                const int dz = z - 1 + kd;
                if (dz < 0 || (dz & 1)) continue;
                const int iz = dz >> 1;
                if (iz >= Di) continue;

                const float* prow = inc + ((size_t)iz * Hi + yp) * Wi;
                float r[TX / 2 + 1], s[TX / 2 + 1];
                const float2 v = *reinterpret_cast<const float2*>(prow + i0);
                r[0] = v.x; r[1] = v.y;
                r[2] = xe ? prow[i0 + 2] : 0.f;
                if (hb) {
                    const float* qrow = prow + Wi;
                    const float2 u = *reinterpret_cast<const float2*>(qrow + i0);
                    s[0] = u.x; s[1] = u.y;
                    s[2] = xe ? qrow[i0 + 2] : 0.f;
                } else {
                    s[0] = s[1] = s[2] = 0.f;
                }

                const float* swp = sw + cl * 27 + kd * 9;
#pragma unroll
                for (int g = 0; g < CG; g++) {
                    const float* wb = swp + g * chunk * 27;
                    const float wa0 = wb[3], wa1 = wb[4], wa2 = wb[5]; // kh=1, even y (row r)
                    const float wb0 = wb[0], wb1 = wb[1], wb2 = wb[2]; // kh=0, odd y  (row r)
                    const float wc0 = wb[6], wc1 = wb[7], wc2 = wb[8]; // kh=2, odd y  (row s)
#pragma unroll
                    for (int e = 0; e < TX / 2; e++) {
                        // even-y outputs
                        acc[g][2 * e]          = fmaf(r[e], wa1, acc[g][2 * e]);
                        acc[g][2 * e + 1]      = fmaf(r[e], wa0,
                                                 fmaf(r[e + 1], wa2, acc[g][2 * e + 1]));
                        // odd-y outputs
                        acc[g][TX + 2 * e]     = fmaf(r[e], wb1,
                                                 fmaf(s[e], wc1, acc[g][TX + 2 * e]));
                        acc[g][TX + 2 * e + 1] = fmaf(r[e], wb0,
                                                 fmaf(r[e + 1], wb2,
                                                 fmaf(s[e], wc0,
                                                 fmaf(s[e + 1], wc2, acc[g][TX + 2 * e + 1]))));
                    }
                }
            }
        }
    }

#pragma unroll
    for (int g = 0; g < CG; g++)
#pragma unroll
        for (int p = 0; p < 2; p++) {
            const int yo = 2 * yp + p;
            float* orow = out + (((size_t)(cb + g) * Do + z) * Ho + yo) * Wo + x0;
            *reinterpret_cast<float4*>(orow) =
                make_float4(acc[g][p * TX + 0], acc[g][p * TX + 1],
                            acc[g][p * TX + 2], acc[g][p * TX + 3]);
        }
    if (STATS)
        stats_epilogue<CG, 2 * TX>(
            reinterpret_cast<const float(*)[2 * TX]>(acc), part, cb, tid, nthr);
}

// ---------------------------------------------------------------------------
// BN finalize + apply.
// ---------------------------------------------------------------------------
__global__ void bn_stats_final(const double2* __restrict__ part,
                               float2* __restrict__ mstd,
                               int P, int V, float eps) {
    const int c = blockIdx.x;
    double s = 0.0, q = 0.0;
    for (int i = threadIdx.x; i < P; i += 256) {
        const double2 pp = part[(size_t)c * PMAX_ + i];
        s += pp.x; q += pp.y;
    }
    __shared__ double ss[256], sq[256];
    ss[threadIdx.x] = s; sq[threadIdx.x] = q;
    __syncthreads();
    for (int o = 128; o > 0; o >>= 1) {
        if (threadIdx.x < o) {
            ss[threadIdx.x] += ss[threadIdx.x + o];
            sq[threadIdx.x] += sq[threadIdx.x + o];
        }
        __syncthreads();
    }
    if (threadIdx.x == 0) {
        const double mean = ss[0] / V;
        const double var  = sq[0] / V - mean * mean;
        mstd[c] = make_float2((float)mean, (float)(1.0 / sqrt(var + (double)eps)));
    }
}

__global__ void bn_apply(float4* __restrict__ x,
                         const float2* __restrict__ mstd,
                         const float* __restrict__ gam,
                         const float* __restrict__ bet, int Vq) {
    const int c = blockIdx.y;
    const size_t i = (size_t)c * Vq + (size_t)blockIdx.x * blockDim.x + threadIdx.x;
    const float2 ms = mstd[c];
    const float a = ms.y * gam[c];
    const float b = fmaf(-ms.x, a, bet[c]);
    float4 v = x[i];
    v.x = fmaxf(fmaf(v.x, a, b), 0.f);
    v.y = fmaxf(fmaf(v.y, a, b), 0.f);
    v.z = fmaxf(fmaf(v.z, a, b), 0.f);
    v.w = fmaxf(fmaf(v.w, a, b), 0.f);
    x[i] = v;
}

// ---------------------------------------------------------------------------
// Host orchestration
// ---------------------------------------------------------------------------
static void run_bn(float* buf, int C, int V, int P, const float* g, const float* b,
                   double2* part, float2* mstd) {
    bn_stats_final<<<C, 256>>>(part, mstd, P, V, 1e-5f);
    const int vq = V / 4;
    const int bs = (vq >= 256) ? 256 : vq;
    bn_apply<<<dim3(vq / bs, C), bs>>>((float4*)buf, mstd, g, b, vq);
}

extern "C" void kernel_launch(void* const* d_in, const int* in_sizes, int n_in,
                              void* d_out, int out_size) {
    (void)in_sizes; (void)n_in; (void)out_size;

    const float* x     = (const float*)d_in[0];
    const float* w0    = (const float*)d_in[1];
    const float* g0    = (const float*)d_in[2];
    const float* b0    = (const float*)d_in[3];
    const float* w1    = (const float*)d_in[4];
    const float* g1    = (const float*)d_in[5];
    const float* b1    = (const float*)d_in[6];
    const float* w2    = (const float*)d_in[7];
    const float* g2    = (const float*)d_in[8];
    const float* b2    = (const float*)d_in[9];
    const float* w3    = (const float*)d_in[10];
    const float* g3    = (const float*)d_in[11];
    const float* b3    = (const float*)d_in[12];
    const float* wt3   = (const float*)d_in[13];
    const float* gt3   = (const float*)d_in[14];
    const float* bt3   = (const float*)d_in[15];
    const float* wt2   = (const float*)d_in[16];
    const float* gt2   = (const float*)d_in[17];
    const float* bt2   = (const float*)d_in[18];
    const float* wt1   = (const float*)d_in[19];
    const float* gt1   = (const float*)d_in[20];
    const float* bt1   = (const float*)d_in[21];
    const float* w_out = (const float*)d_in[22];

    float *cat0, *cat1, *cat2, *s8;
    double2* part;
    float2* mstd;
    cudaGetSymbolAddress((void**)&cat0, g_cat0);
    cudaGetSymbolAddress((void**)&cat1, g_cat1);
    cudaGetSymbolAddress((void**)&cat2, g_cat2);
    cudaGetSymbolAddress((void**)&s8,   g_s8);
    cudaGetSymbolAddress((void**)&part, g_part);
    cudaGetSymbolAddress((void**)&mstd, g_mstd);

    float* s1 = cat0 + (size_t)24 * V0_;
    float* s2 = cat1 + (size_t)32 * V1_;
    float* s4 = cat2 + (size_t)32 * V2_;

    // ---- encoder ----
    // conv0: 8->8, 128^3, stride 1
    conv_s1_kernel<8, 1, 8, true><<<dim3(16, 128, 1), dim3(16, 8), 8 * 8 * 27 * 4>>>(
        x, w0, s1, part, 8, 128, 128, 128);
    run_bn(s1, 8, V0_, 16 * 128, g0, b0, part, mstd);

    // conv1: 8->16, stride 2 -> 64^3 (CG=8 for occupancy)
    conv_s2_kernel<8, 4, true><<<dim3(8, 64, 2), dim3(16, 8), 8 * 8 * 27 * 4>>>(
        s1, w1, s2, part, 8, 128, 128, 128, 64, 64, 64);
    run_bn(s2, 16, V1_, 8 * 64, g1, b1, part, mstd);

    // conv2: 16->32, stride 2 -> 32^3
    conv_s2_kernel<8, 4, true><<<dim3(4, 32, 4), dim3(8, 8), 8 * 16 * 27 * 4>>>(
        s2, w2, s4, part, 16, 64, 64, 64, 32, 32, 32);
    run_bn(s4, 32, V2_, 4 * 32, g2, b2, part, mstd);

    // conv3: 32->64, stride 2 -> 16^3
    conv_s2_kernel<8, 4, true><<<dim3(1, 16, 8), dim3(4, 16), 8 * 32 * 27 * 4>>>(
        s4, w3, s8, part, 32, 32, 32, 32, 16, 16, 16);
    run_bn(s8, 64, V3_, 1 * 16, g3, b3, part, mstd);

    // ---- decoder ----
    // tconv3: 64->32, 16^3 -> 32^3 (y-pair: block covers 16 yo)
    tconv_kernel<8, 4, true><<<dim3(2, 32, 4), dim3(8, 8), 8 * 32 * 27 * 4>>>(
        s8, wt3, cat2, part, 64, 16, 16, 16);
    run_bn(cat2, 32, V2_, 2 * 32, gt3, bt3, part, mstd);

    // tconv2: 64->32, 32^3 -> 64^3
    tconv_kernel<8, 4, true><<<dim3(4, 64, 4), dim3(16, 8), 8 * 32 * 27 * 4>>>(
        cat2, wt2, cat1, part, 64, 32, 32, 32);
    run_bn(cat1, 32, V1_, 4 * 64, gt2, bt2, part, mstd);

    // tconv1: 48->24, 64^3 -> 128^3
    tconv_kernel<8, 4, true><<<dim3(16, 128, 3), dim3(32, 4), 8 * 32 * 27 * 4>>>(
        cat1, wt1, cat0, part, 48, 64, 64, 64);
    run_bn(cat0, 24, V0_, 16 * 128, gt1, bt1, part, mstd);

    // conv_out: 32->2, 128^3, stride 1, TZ=2 (no BN/ReLU)
    conv_s1_kernel<2, 2, 8, false><<<dim3(16, 64, 1), dim3(16, 8), 2 * 32 * 27 * 4>>>(
        cat0, w_out, (float*)d_out, nullptr, 32, 128, 128, 128);
}